// round 1
// baseline (speedup 1.0000x reference)
#include <cuda_runtime.h>

// Problem constants
#define CB    128          // input channels
#define HH    56
#define WW    56
#define NPIX  3136         // 56*56
#define BATCH 8
#define NTOT  25088        // BATCH * NPIX
#define KTOT  1152         // CB * 9
#define OUTC  128

// Scratch (static __device__ allowed; cudaMalloc is not)
__device__ float g_off[BATCH * 18 * NPIX];          // offset conv output, ~1.8 MB
__device__ float g_col[(size_t)KTOT * NTOT];        // im2col-after-deform, ~115.6 MB

// ---------------------------------------------------------------------------
// Kernel 1: offset prediction conv  (128 -> 18 channels, 3x3, pad 1)
// thread = one output element (b, j, y, x); x fastest -> coalesced x reads,
// weight reads broadcast within warp.
// ---------------------------------------------------------------------------
__global__ void offset_conv_kernel(const float* __restrict__ x,
                                   const float* __restrict__ w,
                                   const float* __restrict__ bias) {
    int t = blockIdx.x * blockDim.x + threadIdx.x;
    if (t >= BATCH * 18 * NPIX) return;
    int xw = t % WW;
    int y  = (t / WW) % HH;
    int j  = (t / NPIX) % 18;
    int b  = t / (NPIX * 18);

    float acc = __ldg(bias + j);
    const float* xb = x + (size_t)b * CB * NPIX;
    const float* wj = w + j * CB * 9;
    int y0 = y - 1, x0 = xw - 1;

    for (int c = 0; c < CB; ++c) {
        const float* xc = xb + c * NPIX;
        const float* wc = wj + c * 9;
        #pragma unroll
        for (int ky = 0; ky < 3; ++ky) {
            int yy = y0 + ky;
            if (yy < 0 || yy >= HH) continue;
            #pragma unroll
            for (int kx = 0; kx < 3; ++kx) {
                int xx = x0 + kx;
                if (xx < 0 || xx >= WW) continue;
                acc = fmaf(__ldg(wc + ky * 3 + kx), __ldg(xc + yy * WW + xx), acc);
            }
        }
    }
    g_off[t] = acc;
}

// ---------------------------------------------------------------------------
// Kernel 2: deformable bilinear sampling -> col[k = c*9+n][np = b*3136+pix]
// thread = (b, n, pix); weights/indices computed once, then loop over c=0..127.
// Stores are coalesced (consecutive threads = consecutive pix).
// Replicates the reference's trunc() quirk exactly.
// ---------------------------------------------------------------------------
__global__ void sample_kernel(const float* __restrict__ x) {
    int t = blockIdx.x * blockDim.x + threadIdx.x;
    if (t >= BATCH * 9 * NPIX) return;
    int pix = t % NPIX;
    int n   = (t / NPIX) % 9;
    int b   = t / (NPIX * 9);
    int y   = pix / WW, xw = pix % WW;

    float off_y = g_off[(size_t)(b * 18 + n) * NPIX + pix];
    float off_x = g_off[(size_t)(b * 18 + n + 9) * NPIX + pix];

    // p = p0 + pn + offset;  p0y = y+1, pn_y = ky-1  =>  p_y = y + ky + off_y
    float p_y = (float)(y + n / 3) + off_y;
    float p_x = (float)(xw + n % 3) + off_x;

    float qy = floorf(p_y), qx = floorf(p_x);
    float qlt_y = fminf(fmaxf(qy, 0.f), 57.f);
    float qlt_x = fminf(fmaxf(qx, 0.f), 57.f);
    float qrb_y = fminf(fmaxf(qy + 1.f, 0.f), 57.f);
    float qrb_x = fminf(fmaxf(qx + 1.f, 0.f), 57.f);
    float py = fminf(fmaxf(p_y, 0.f), 57.f);
    float px = fminf(fmaxf(p_x, 0.f), 57.f);

    float g_lt = (1.f - (py - qlt_y)) * truncf(1.f - (px - qlt_x));
    float g_rb = (1.f - (qrb_y - py)) * truncf(1.f - (qrb_x - px));
    float g_lb = (1.f - (py - qlt_y)) * (1.f - (qrb_x - px));
    float g_rt = (1.f - (qrb_y - py)) * (1.f - (px - qlt_x));

    int iy_lt = (int)qlt_y, ix_lt = (int)qlt_x;
    int iy_rb = (int)qrb_y, ix_rb = (int)qrb_x;

    // taps index the padded map; map to unpadded x, zero outside ring
    int o0 = (iy_lt - 1) * WW + (ix_lt - 1);   // (lt_y, lt_x)
    int o1 = (iy_rb - 1) * WW + (ix_rb - 1);   // (rb_y, rb_x)
    int o2 = (iy_lt - 1) * WW + (ix_rb - 1);   // (lt_y, rb_x)  -> g_lb
    int o3 = (iy_rb - 1) * WW + (ix_lt - 1);   // (rb_y, lt_x)  -> g_rt

    bool vy_lt = (iy_lt >= 1) && (iy_lt <= 56);
    bool vx_lt = (ix_lt >= 1) && (ix_lt <= 56);
    bool vy_rb = (iy_rb >= 1) && (iy_rb <= 56);
    bool vx_rb = (ix_rb >= 1) && (ix_rb <= 56);

    float w0 = (vy_lt && vx_lt) ? g_lt : 0.f;
    float w1 = (vy_rb && vx_rb) ? g_rb : 0.f;
    float w2 = (vy_lt && vx_rb) ? g_lb : 0.f;
    float w3 = (vy_rb && vx_lt) ? g_rt : 0.f;

    const float* xb = x + (size_t)b * CB * NPIX;
    float* colp = g_col + (size_t)n * NTOT + (size_t)b * NPIX + pix;

    for (int c = 0; c < CB; ++c) {
        const float* xc = xb + (size_t)c * NPIX;
        float v = 0.f;
        if (w0 != 0.f) v = fmaf(w0, __ldg(xc + o0), v);
        if (w1 != 0.f) v = fmaf(w1, __ldg(xc + o1), v);
        if (w2 != 0.f) v = fmaf(w2, __ldg(xc + o2), v);
        if (w3 != 0.f) v = fmaf(w3, __ldg(xc + o3), v);
        colp[(size_t)c * 9 * NTOT] = v;
    }
}

// ---------------------------------------------------------------------------
// Kernel 3: SGEMM  C[o][np] = sum_k A[o][k] * col[k][np]
// A = conv_w flattened [128][1152] (k = c*9+n is its native inner order).
// Tile 128(M) x 64(N), BK=16, 128 threads, 8x8 micro-tile with split fragments
// (tm*4 / 64+tm*4, tn*4 / 32+tn*4) -> conflict-free LDS.128.
// ---------------------------------------------------------------------------
#define BM 128
#define BN 64
#define BK 16

__global__ __launch_bounds__(128) void gemm_kernel(const float* __restrict__ A,
                                                   float* __restrict__ out) {
    __shared__ float As[BK][BM];
    __shared__ float Bs[BK][BN];

    int n0  = blockIdx.x * BN;
    int tid = threadIdx.x;
    int tm  = tid / 8;   // 0..15
    int tn  = tid % 8;   // 0..7

    float acc[8][8];
    #pragma unroll
    for (int i = 0; i < 8; ++i)
        #pragma unroll
        for (int j = 0; j < 8; ++j) acc[i][j] = 0.f;

    for (int k0 = 0; k0 < KTOT; k0 += BK) {
        // A tile: 128x16 = 2048 elems, 16 per thread (16 consecutive per row)
        #pragma unroll
        for (int i = 0; i < 16; ++i) {
            int e  = tid + i * 128;
            int m  = e / BK;
            int kk = e % BK;
            As[kk][m] = __ldg(A + (size_t)m * KTOT + k0 + kk);
        }
        // B tile: 16x64 = 1024 elems, 8 per thread, fully coalesced along np
        #pragma unroll
        for (int i = 0; i < 8; ++i) {
            int e  = tid + i * 128;
            int kk = e / BN;
            int nn = e % BN;
            Bs[kk][nn] = g_col[(size_t)(k0 + kk) * NTOT + n0 + nn];
        }
        __syncthreads();

        #pragma unroll
        for (int kk = 0; kk < BK; ++kk) {
            float4 a0 = *(const float4*)&As[kk][tm * 4];
            float4 a1 = *(const float4*)&As[kk][64 + tm * 4];
            float4 b0 = *(const float4*)&Bs[kk][tn * 4];
            float4 b1 = *(const float4*)&Bs[kk][32 + tn * 4];
            float a[8] = {a0.x, a0.y, a0.z, a0.w, a1.x, a1.y, a1.z, a1.w};
            float bf[8] = {b0.x, b0.y, b0.z, b0.w, b1.x, b1.y, b1.z, b1.w};
            #pragma unroll
            for (int i = 0; i < 8; ++i)
                #pragma unroll
                for (int j = 0; j < 8; ++j)
                    acc[i][j] = fmaf(a[i], bf[j], acc[i][j]);
        }
        __syncthreads();
    }

    // store: out[b][o][pix] with np = b*3136 + pix
    #pragma unroll
    for (int i = 0; i < 8; ++i) {
        int m = (i < 4) ? (tm * 4 + i) : (64 + tm * 4 + (i - 4));
        #pragma unroll
        for (int j = 0; j < 8; ++j) {
            int nl  = (j < 4) ? (tn * 4 + j) : (32 + tn * 4 + (j - 4));
            int np  = n0 + nl;
            int b   = np / NPIX;
            int pix = np % NPIX;
            out[(size_t)b * OUTC * NPIX + (size_t)m * NPIX + pix] = acc[i][j];
        }
    }
}

// ---------------------------------------------------------------------------
extern "C" void kernel_launch(void* const* d_in, const int* in_sizes, int n_in,
                              void* d_out, int out_size) {
    const float* x  = (const float*)d_in[0];   // [8,128,56,56]
    const float* ow = (const float*)d_in[1];   // [18,128,3,3]
    const float* ob = (const float*)d_in[2];   // [18]
    const float* cw = (const float*)d_in[3];   // [128,128,3,3]
    float* out = (float*)d_out;                // [8,128,56,56]

    offset_conv_kernel<<<(BATCH * 18 * NPIX + 255) / 256, 256>>>(x, ow, ob);
    sample_kernel<<<(BATCH * 9 * NPIX + 255) / 256, 256>>>(x);
    gemm_kernel<<<NTOT / BN, 128>>>(cw, out);
}